// round 10
// baseline (speedup 1.0000x reference)
#include <cuda_runtime.h>
#include <cstdint>

#define HH 192
#define WW 192
#define CC 80
#define BB 8
#define RSTRIP 4
#define NSTRIP (HH / RSTRIP)     /* 48 */
#define ROWSPC (RSTRIP + 2)      /* 6 rows per channel per strip */
#define NWARP 8
#define NPIX (BB * HH * WW)      /* 294912 */
#define HWA (HH * WW)
#define SPIX (RSTRIP * WW)       /* 768 pixels per strip */
#define THR 0.7f

#define STAGE_CH 16
#define NSTAGE (CC / STAGE_CH)   /* 5 */
#define ROWB (WW * 4)            /* 768 bytes per row */
#define CHB (ROWSPC * ROWB)      /* 4608 bytes per channel slot */
#define STAGEB (STAGE_CH * CHB)  /* 73728 bytes per stage buffer */
#define CHF (ROWSPC * WW)        /* floats per channel slot */
#define STAGEF (STAGE_CH * CHF)  /* floats per stage buffer */
#define SMEM_TOTAL (2 * STAGEB + NWARP * SPIX * 4)  /* 172032 B */

__device__ __forceinline__ uint32_t smem_u32(const void* p) {
    uint32_t r;
    asm("{ .reg .u64 t; cvta.to.shared.u64 t, %1; cvt.u32.u64 %0, t; }"
        : "=r"(r) : "l"(p));
    return r;
}

#define MBAR_INIT(a, cnt) \
    asm volatile("mbarrier.init.shared.b64 [%0], %1;" :: "r"(a), "r"(cnt) : "memory")
#define MBAR_EXPECT_TX(a, bytes) \
    asm volatile("mbarrier.arrive.expect_tx.shared.b64 _, [%0], %1;" :: "r"(a), "r"(bytes) : "memory")
#define MBAR_ARRIVE(a) \
    asm volatile("mbarrier.arrive.shared.b64 _, [%0];" :: "r"(a) : "memory")
#define MBAR_WAIT(a, par) do {                                                   \
    asm volatile(                                                                \
        "{\n\t.reg .pred P1;\n\t"                                                \
        "WAIT_LOOP_%=:\n\t"                                                      \
        "mbarrier.try_wait.parity.acquire.cta.shared::cta.b64 P1, [%0], %1, 0x989680;\n\t" \
        "@P1 bra.uni WAIT_DONE_%=;\n\t"                                          \
        "bra.uni WAIT_LOOP_%=;\n\t"                                              \
        "WAIT_DONE_%=:\n\t}"                                                     \
        :: "r"(a), "r"(par) : "memory");                                         \
} while (0)
#define BULK_G2S(dst, src, bytes, mbar) \
    asm volatile("cp.async.bulk.shared::cluster.global.mbarrier::complete_tx::bytes " \
                 "[%0], [%1], %2, [%3];" \
                 :: "r"(dst), "l"(src), "r"(bytes), "r"(mbar) : "memory")

// lr[i] = max(left, right neighbor) within the row (borders -> 0; heat >= 0)
__device__ __forceinline__ void row_lr6(const float v[6], float lr[6], int lane) {
    float vl = __shfl_up_sync(0xffffffffu, v[5], 1);
    float vr = __shfl_down_sync(0xffffffffu, v[0], 1);
    vl = (lane == 0) ? 0.0f : vl;
    vr = (lane == 31) ? 0.0f : vr;
    lr[0] = fmaxf(vl, v[1]);
    lr[1] = fmaxf(v[0], v[2]);
    lr[2] = fmaxf(v[1], v[3]);
    lr[3] = fmaxf(v[2], v[4]);
    lr[4] = fmaxf(v[3], v[5]);
    lr[5] = fmaxf(v[4], vr);
}

__device__ __forceinline__ void lds_row6(const float* p, float v[6]) {
    const float2* q = reinterpret_cast<const float2*>(p);
    float2 a = q[0], b = q[1], c = q[2];
    v[0] = a.x; v[1] = a.y; v[2] = b.x; v[3] = b.y; v[4] = c.x; v[5] = c.y;
}

// One block per (batch, 4-row strip). Heat rows stream in via cp.async.bulk
// (TMA path, no SM LSU) into a 2-deep smem pipeline of 16-channel stages.
// 8 consumer warps each handle 2 channels/stage with the rolling 3x3 NMS.
__global__ void __launch_bounds__(256)
fused_kernel(const float* __restrict__ heat, const float* __restrict__ box,
             float* __restrict__ out) {
    extern __shared__ float dyn[];
    float* buf0 = dyn;
    float* buf1 = dyn + STAGEF;
    float* smem_s = dyn + 2 * STAGEF;               // [NWARP][SPIX]
    __shared__ unsigned long long mb[4];            // full0, full1, empty0, empty1

    const int strip = blockIdx.x;
    const int b     = blockIdx.y;
    const int tid   = threadIdx.x;
    const int wid   = tid >> 5;
    const int lane  = tid & 31;
    const int x0 = lane * 6;
    const int y0 = strip * RSTRIP;

    const uint32_t mb_base = smem_u32(mb);
    const uint32_t full_a[2]  = { mb_base, mb_base + 8 };
    const uint32_t empty_a[2] = { mb_base + 16, mb_base + 24 };
    const uint32_t buf_a[2] = { smem_u32(buf0), smem_u32(buf1) };

    // Per-block row clamp (contiguous rows lo..hi exist; others pre-zeroed).
    const int lo = (y0 - 1 < 0) ? 0 : y0 - 1;
    const int hi = (y0 + RSTRIP > HH - 1) ? HH - 1 : y0 + RSTRIP;
    const int nrows = hi - lo + 1;
    const uint32_t chbytes = nrows * ROWB;
    const uint32_t stage_bytes = STAGE_CH * chbytes;
    const uint32_t dstoff = (lo - (y0 - 1)) * ROWB;

    if (tid == 0) {
        MBAR_INIT(full_a[0], 1);
        MBAR_INIT(full_a[1], 1);
        MBAR_INIT(empty_a[0], 256);
        MBAR_INIT(empty_a[1], 256);
    }
    // Pre-zero missing halo slots (TMA never writes them; persists across stages).
    if (strip == 0)
        for (int i = tid; i < 2 * STAGE_CH * WW; i += 256) {
            int bb_ = i / (STAGE_CH * WW), rest = i % (STAGE_CH * WW);
            dyn[bb_ * STAGEF + (rest / WW) * CHF + 0 * WW + (rest % WW)] = 0.0f;
        }
    if (strip == NSTRIP - 1)
        for (int i = tid; i < 2 * STAGE_CH * WW; i += 256) {
            int bb_ = i / (STAGE_CH * WW), rest = i % (STAGE_CH * WW);
            dyn[bb_ * STAGEF + (rest / WW) * CHF + (ROWSPC - 1) * WW + (rest % WW)] = 0.0f;
        }
    __syncthreads();
    asm volatile("fence.proxy.async.shared::cta;" ::: "memory");

    const float* hb = heat + (size_t)b * CC * HWA + lo * WW;

    // Prologue: fill stage 0 (buffer 0).
    if (tid == 0) {
        MBAR_EXPECT_TX(full_a[0], stage_bytes);
#pragma unroll 1
        for (int cs = 0; cs < STAGE_CH; cs++)
            BULK_G2S(buf_a[0] + cs * CHB + dstoff, hb + cs * HWA, chbytes, full_a[0]);
    }

    float s[RSTRIP][6];
#pragma unroll
    for (int r = 0; r < RSTRIP; r++)
#pragma unroll
        for (int i = 0; i < 6; i++) s[r][i] = 0.0f;

#pragma unroll 1
    for (int st = 0; st < NSTAGE; st++) {
        // Producer: launch stage st+1 into the other buffer.
        if (tid == 0 && st + 1 < NSTAGE) {
            const int t = st + 1, bsel = t & 1, u = t >> 1;
            if (u >= 1) MBAR_WAIT(empty_a[bsel], (u - 1) & 1);
            MBAR_EXPECT_TX(full_a[bsel], stage_bytes);
#pragma unroll 1
            for (int cs = 0; cs < STAGE_CH; cs++)
                BULK_G2S(buf_a[bsel] + cs * CHB + dstoff,
                         hb + (t * STAGE_CH + cs) * HWA, chbytes, full_a[bsel]);
        }

        MBAR_WAIT(full_a[st & 1], (st >> 1) & 1);

        // Consume: warp wid -> channel slots {2*wid, 2*wid+1}, interleaved for ILP.
        const float* base = ((st & 1) ? buf1 : buf0) + (2 * wid) * CHF + x0;
        const float* p[2] = { base, base + CHF };

        float v_c[2][6], lr_c[2][6], h_m1[2][6];
#pragma unroll
        for (int k = 0; k < 2; k++) {
            float vt[6], lrt[6];
            lds_row6(p[k], vt);                 // row slot 0 = y0-1
            row_lr6(vt, lrt, lane);
#pragma unroll
            for (int i = 0; i < 6; i++) h_m1[k][i] = fmaxf(lrt[i], vt[i]);
            lds_row6(p[k] + WW, v_c[k]);        // row slot 1 = y0
            row_lr6(v_c[k], lr_c[k], lane);
        }

#pragma unroll
        for (int r = 0; r < RSTRIP; r++) {
            float v_n[2][6], lr_n[2][6];
            lds_row6(p[0] + (r + 2) * WW, v_n[0]);
            lds_row6(p[1] + (r + 2) * WW, v_n[1]);
            row_lr6(v_n[0], lr_n[0], lane);
            row_lr6(v_n[1], lr_n[1], lane);
#pragma unroll
            for (int k = 0; k < 2; k++)
#pragma unroll
                for (int i = 0; i < 6; i++) {
                    float hp1 = fmaxf(lr_n[k][i], v_n[k][i]);
                    float Bv = fmaxf(fmaxf(h_m1[k][i], hp1), lr_c[k][i]);
                    if (v_c[k][i] >= Bv) s[r][i] = fmaxf(s[r][i], v_c[k][i]);
                }
#pragma unroll
            for (int k = 0; k < 2; k++)
#pragma unroll
                for (int i = 0; i < 6; i++) {
                    h_m1[k][i] = fmaxf(lr_c[k][i], v_c[k][i]);
                    v_c[k][i] = v_n[k][i];
                    lr_c[k][i] = lr_n[k][i];
                }
        }

        MBAR_ARRIVE(empty_a[st & 1]);
    }

    // Publish per-warp partials and reduce + decode.
#pragma unroll
    for (int r = 0; r < RSTRIP; r++)
#pragma unroll
        for (int i = 0; i < 6; i++)
            smem_s[wid * SPIX + r * WW + x0 + i] = s[r][i];

    __syncthreads();

    // Output layout (float32, reference return order):
    //   [0, 4N) boxes [B,H,W,4] | [4N, 5N) mask | [5N, 6N) scores | [6N, 8N) center
    for (int pix = tid; pix < SPIX; pix += 256) {
        float sc = smem_s[pix];
#pragma unroll
        for (int w = 1; w < NWARP; w++) sc = fmaxf(sc, smem_s[w * SPIX + pix]);
        bool m = sc > THR;

        int x = pix % WW;
        int y = y0 + pix / WW;
        int idx = (b * HH + y) * WW + x;

        const float* bp = box + (b * 4) * HWA + y * WW + x;
        float dx = __ldg(bp);
        float dy = __ldg(bp + HWA);
        float w_ = __ldg(bp + 2 * HWA);
        float h_ = __ldg(bp + 3 * HWA);

        float cx = ((float)x + dx) * 4.0f;
        float cy = ((float)y + dy) * 4.0f;
        float hw = (w_ * 4.0f) * 0.5f;   // exact (power-of-two scales)
        float hh = (h_ * 4.0f) * 0.5f;

        float x1 = fminf(fmaxf(cx - hw, 0.0f), 768.0f);
        float y1 = fminf(fmaxf(cy - hh, 0.0f), 768.0f);
        float x2 = fminf(fmaxf(cx + hw, 0.0f), 768.0f);
        float y2 = fminf(fmaxf(cy + hh, 0.0f), 768.0f);

        float4 bx = m ? make_float4(x1, y1, x2 - x1, y2 - y1)
                      : make_float4(0.f, 0.f, 0.f, 0.f);
        reinterpret_cast<float4*>(out)[idx] = bx;

        out[NPIX * 4 + idx] = m ? 1.0f : 0.0f;
        out[NPIX * 5 + idx] = m ? sc : 0.0f;

        float2 ct = m ? make_float2(cx, cy) : make_float2(0.f, 0.f);
        reinterpret_cast<float2*>(out + NPIX * 6)[idx] = ct;
    }
}

extern "C" void kernel_launch(void* const* d_in, const int* in_sizes, int n_in,
                              void* d_out, int out_size) {
    const float* heat = (const float*)d_in[0];
    const float* box  = (const float*)d_in[1];
    // Robust input identification: heat has 23,592,960 elements, box 1,179,648.
    if (n_in >= 2 && in_sizes[0] < in_sizes[1]) {
        const float* t = heat; heat = box; box = t;
    }
    float* out = (float*)d_out;

    cudaFuncSetAttribute(fused_kernel, cudaFuncAttributeMaxDynamicSharedMemorySize,
                         SMEM_TOTAL);
    fused_kernel<<<dim3(NSTRIP, BB), 256, SMEM_TOTAL>>>(heat, box, out);
}

// round 11
// speedup vs baseline: 1.0174x; 1.0174x over previous
#include <cuda_runtime.h>

#define HH 192
#define WW 192
#define CC 80
#define BB 8
#define NPIX (BB * HH * WW)    /* 294912 */
#define HWA (HH * WW)
#define THR 0.7f
#define WROWS 12               /* rows per warp */
#define HALF (HH / 2)          /* 96 rows per block */

// Score scratch: int bits of fp32 score (positive floats order-preserve as int).
__device__ int g_score_bits[NPIX];

__global__ void init_kernel() {
    int i = blockIdx.x * blockDim.x + threadIdx.x;
    if (i < NPIX / 4)
        reinterpret_cast<int4*>(g_score_bits)[i] = make_int4(0, 0, 0, 0);
}

__device__ __forceinline__ void load_row6(const float* __restrict__ p, int y, float v[6]) {
    if ((unsigned)y < (unsigned)HH) {
        const float2* q = reinterpret_cast<const float2*>(p + y * WW);
        float2 a = __ldg(q);
        float2 b = __ldg(q + 1);
        float2 c = __ldg(q + 2);
        v[0] = a.x; v[1] = a.y; v[2] = b.x; v[3] = b.y; v[4] = c.x; v[5] = c.y;
    } else {
#pragma unroll
        for (int i = 0; i < 6; i++) v[i] = 0.0f;
    }
}

// lr[i] = max(left, right neighbor) within the row (borders -> 0; heat >= 0)
__device__ __forceinline__ void row_lr6(const float v[6], float lr[6], int lane) {
    float vl = __shfl_up_sync(0xffffffffu, v[5], 1);
    float vr = __shfl_down_sync(0xffffffffu, v[0], 1);
    vl = (lane == 0) ? 0.0f : vl;
    vr = (lane == 31) ? 0.0f : vr;
    lr[0] = fmaxf(vl, v[1]);
    lr[1] = fmaxf(v[0], v[2]);
    lr[2] = fmaxf(v[1], v[3]);
    lr[3] = fmaxf(v[2], v[4]);
    lr[4] = fmaxf(v[3], v[5]);
    lr[5] = fmaxf(v[4], vr);
}

// Block = (half-image, channel, batch): each block streams a CONTIGUOUS ~74KB
// run of one channel image (96 rows + halo). Warp w owns 12 consecutive rows;
// lane l owns columns [6l, 6l+6). Rolling 3x3-max pipeline; kept peaks above
// the threshold are pushed straight to the score scratch via no-return atomics
// (~10% density, spread addresses).
__global__ void __launch_bounds__(256) nms_kernel(const float* __restrict__ heat) {
    const int half = blockIdx.x;
    const int c    = blockIdx.y;
    const int b    = blockIdx.z;
    const int wid  = threadIdx.x >> 5;
    const int lane = threadIdx.x & 31;
    const int x0 = lane * 6;
    const int y0 = half * HALF + wid * WROWS;

    const float* pl = heat + ((size_t)b * CC + c) * HWA + x0;

    float v_c[6], lr_c[6], h_m1[6];
    {   // halo row y0-1 -> h(y0-1)
        float vt[6], lrt[6];
        load_row6(pl, y0 - 1, vt);
        row_lr6(vt, lrt, lane);
#pragma unroll
        for (int i = 0; i < 6; i++) h_m1[i] = fmaxf(lrt[i], vt[i]);
    }
    load_row6(pl, y0, v_c);
    row_lr6(v_c, lr_c, lane);

    const int pb = (b * HH + y0) * WW + x0;

#pragma unroll
    for (int r = 0; r < WROWS; r++) {
        float v_n[6], lr_n[6];
        load_row6(pl, y0 + r + 1, v_n);
        row_lr6(v_n, lr_n, lane);

        // kept <=> v >= max(h(y-1), h(y+1), lrmax(y))   (h(y) >= v trivially)
#pragma unroll
        for (int i = 0; i < 6; i++) {
            float hp1 = fmaxf(lr_n[i], v_n[i]);
            float Bv = fmaxf(fmaxf(h_m1[i], hp1), lr_c[i]);
            if (v_c[i] >= Bv && v_c[i] > THR)
                atomicMax(&g_score_bits[pb + r * WW + i], __float_as_int(v_c[i]));
        }
        // rotate pipeline (register renames under full unroll)
#pragma unroll
        for (int i = 0; i < 6; i++) {
            h_m1[i] = fmaxf(lr_c[i], v_c[i]);
            v_c[i] = v_n[i];
            lr_c[i] = lr_n[i];
        }
    }
}

// Output layout (float32, reference return order):
//   [0, 4N) boxes [B,H,W,4] | [4N, 5N) mask | [5N, 6N) scores | [6N, 8N) center
__global__ void __launch_bounds__(256) decode_kernel(const float* __restrict__ box,
                                                     float* __restrict__ out) {
    int idx = blockIdx.x * blockDim.x + threadIdx.x;
    if (idx >= NPIX) return;
    int x = idx % WW;
    int y = (idx / WW) % HH;
    int b = idx / (WW * HH);

    float s = __int_as_float(g_score_bits[idx]);
    bool m = s > THR;

    const float* bp = box + (size_t)b * 4 * HWA + y * WW + x;
    float dx = __ldg(bp);
    float dy = __ldg(bp + HWA);
    float w  = __ldg(bp + 2 * HWA);
    float h  = __ldg(bp + 3 * HWA);

    float cx = ((float)x + dx) * 4.0f;
    float cy = ((float)y + dy) * 4.0f;
    float hw = (w * 4.0f) * 0.5f;   // exact (power-of-two scales)
    float hh = (h * 4.0f) * 0.5f;

    float x1 = fminf(fmaxf(cx - hw, 0.0f), 768.0f);
    float y1 = fminf(fmaxf(cy - hh, 0.0f), 768.0f);
    float x2 = fminf(fmaxf(cx + hw, 0.0f), 768.0f);
    float y2 = fminf(fmaxf(cy + hh, 0.0f), 768.0f);

    float4 bx = m ? make_float4(x1, y1, x2 - x1, y2 - y1)
                  : make_float4(0.f, 0.f, 0.f, 0.f);
    reinterpret_cast<float4*>(out)[idx] = bx;

    out[NPIX * 4 + idx] = m ? 1.0f : 0.0f;
    out[NPIX * 5 + idx] = m ? s : 0.0f;

    float2 ct = m ? make_float2(cx, cy) : make_float2(0.f, 0.f);
    reinterpret_cast<float2*>(out + NPIX * 6)[idx] = ct;
}

extern "C" void kernel_launch(void* const* d_in, const int* in_sizes, int n_in,
                              void* d_out, int out_size) {
    const float* heat = (const float*)d_in[0];
    const float* box  = (const float*)d_in[1];
    // Robust input identification: heat has 23,592,960 elements, box 1,179,648.
    if (n_in >= 2 && in_sizes[0] < in_sizes[1]) {
        const float* t = heat; heat = box; box = t;
    }
    float* out = (float*)d_out;

    init_kernel<<<(NPIX / 4 + 255) / 256, 256>>>();
    nms_kernel<<<dim3(2, CC, BB), 256>>>(heat);
    decode_kernel<<<(NPIX + 255) / 256, 256>>>(box, out);
}

// round 14
// speedup vs baseline: 1.5444x; 1.5181x over previous
#include <cuda_runtime.h>

#define HH 192
#define WW 192
#define CC 80
#define BB 8
#define RSTRIP 2
#define NSTRIP (HH / RSTRIP)   /* 96 */
#define NWARP 8
#define CPG (CC / NWARP)       /* 10 */
#define NPIX (BB * HH * WW)    /* 294912 */
#define HWA (HH * WW)
#define SPIX (RSTRIP * WW)     /* 384 pixels per strip */
#define THR 0.7f

// Plain cached global load (generic path, not .nc): the one load path not yet tried.
__device__ __forceinline__ float2 ldg_f2(const float* p) {
    float2 v;
    asm volatile("ld.global.v2.f32 {%0, %1}, [%2];"
                 : "=f"(v.x), "=f"(v.y) : "l"(p));
    return v;
}

__device__ __forceinline__ void load_row6(const float* __restrict__ p, int y, float v[6]) {
    if ((unsigned)y < (unsigned)HH) {
        const float* q = p + y * WW;
        float2 a = ldg_f2(q);
        float2 b = ldg_f2(q + 2);
        float2 c = ldg_f2(q + 4);
        v[0] = a.x; v[1] = a.y; v[2] = b.x; v[3] = b.y; v[4] = c.x; v[5] = c.y;
    } else {
#pragma unroll
        for (int i = 0; i < 6; i++) v[i] = 0.0f;
    }
}

// lr[i] = max(left neighbor, right neighbor) within the row (borders -> 0; heat >= 0)
__device__ __forceinline__ void row_lr6(const float v[6], float lr[6], int lane) {
    float vl = __shfl_up_sync(0xffffffffu, v[5], 1);
    float vr = __shfl_down_sync(0xffffffffu, v[0], 1);
    vl = (lane == 0) ? 0.0f : vl;
    vr = (lane == 31) ? 0.0f : vr;
    lr[0] = fmaxf(vl, v[1]);
    lr[1] = fmaxf(v[0], v[2]);
    lr[2] = fmaxf(v[1], v[3]);
    lr[3] = fmaxf(v[2], v[4]);
    lr[4] = fmaxf(v[3], v[5]);
    lr[5] = fmaxf(v[4], vr);
}

// One block per (batch, 2-row strip). 8 warps x 10 channels each.
// Lane l owns columns [6l, 6l+6). Rolling horizontal-max pipeline with state
// {h(y-1), v(y), lr(y)}; h(y) = max(lr, v) recomputed at rotation.
// Streaming data (box reads, all output writes) uses evict-first hints so L2
// stays dedicated to the heat halo reuse.
__global__ void __launch_bounds__(256, 4)
fused_kernel(const float* __restrict__ heat, const float* __restrict__ box,
             float* __restrict__ out) {
    __shared__ float smem_s[NWARP][SPIX];

    const int strip = blockIdx.x;
    const int b     = blockIdx.y;
    const int wid   = threadIdx.x >> 5;
    const int lane  = threadIdx.x & 31;
    const int x0 = lane * 6;
    const int y0 = strip * RSTRIP;

    const float* base = heat + (b * CC + wid * CPG) * HWA + x0;

    float s[RSTRIP][6];
#pragma unroll
    for (int r = 0; r < RSTRIP; r++)
#pragma unroll
        for (int i = 0; i < 6; i++) s[r][i] = 0.0f;

#pragma unroll 1
    for (int c = 0; c < CPG; c++) {
        const float* pl = base + c * HWA;

        float v_c[6], lr_c[6], h_m1[6];
        {   // halo row y0-1 -> h(y0-1)
            float vt[6], lrt[6];
            load_row6(pl, y0 - 1, vt);
            row_lr6(vt, lrt, lane);
#pragma unroll
            for (int i = 0; i < 6; i++) h_m1[i] = fmaxf(lrt[i], vt[i]);
        }
        load_row6(pl, y0, v_c);
        row_lr6(v_c, lr_c, lane);

#pragma unroll
        for (int r = 0; r < RSTRIP; r++) {
            float v_n[6], lr_n[6];
            load_row6(pl, y0 + r + 1, v_n);
            row_lr6(v_n, lr_n, lane);

            // kept <=> v >= max(h(y-1), h(y+1), lrmax(y))   (h(y) >= v trivially)
#pragma unroll
            for (int i = 0; i < 6; i++) {
                float hp1 = fmaxf(lr_n[i], v_n[i]);
                float Bv = fmaxf(fmaxf(h_m1[i], hp1), lr_c[i]);
                if (v_c[i] >= Bv) s[r][i] = fmaxf(s[r][i], v_c[i]);
            }
            // rotate pipeline (register renames under full unroll)
#pragma unroll
            for (int i = 0; i < 6; i++) {
                h_m1[i] = fmaxf(lr_c[i], v_c[i]);
                v_c[i] = v_n[i];
                lr_c[i] = lr_n[i];
            }
        }
    }

    // Publish per-warp partials.
#pragma unroll
    for (int r = 0; r < RSTRIP; r++)
#pragma unroll
        for (int i = 0; i < 6; i++)
            smem_s[wid][r * WW + x0 + i] = s[r][i];

    __syncthreads();

    // Reduce over warps + decode + write. 384 pixels / 256 threads.
    // Output layout (float32, reference return order):
    //   [0, 4N) boxes [B,H,W,4] | [4N, 5N) mask | [5N, 6N) scores | [6N, 8N) center
    for (int p = threadIdx.x; p < SPIX; p += 256) {
        float sc = smem_s[0][p];
#pragma unroll
        for (int w = 1; w < NWARP; w++) sc = fmaxf(sc, smem_s[w][p]);
        bool m = sc > THR;

        int x = p % WW;
        int y = y0 + p / WW;
        int idx = (b * HH + y) * WW + x;

        const float* bp = box + (b * 4) * HWA + y * WW + x;
        float dx = __ldcs(bp);                 // zero-reuse: evict-first
        float dy = __ldcs(bp + HWA);
        float w_ = __ldcs(bp + 2 * HWA);
        float h_ = __ldcs(bp + 3 * HWA);

        float cx = ((float)x + dx) * 4.0f;
        float cy = ((float)y + dy) * 4.0f;
        float hw = (w_ * 4.0f) * 0.5f;   // exact (power-of-two scales)
        float hh = (h_ * 4.0f) * 0.5f;

        float x1 = fminf(fmaxf(cx - hw, 0.0f), 768.0f);
        float y1 = fminf(fmaxf(cy - hh, 0.0f), 768.0f);
        float x2 = fminf(fmaxf(cx + hw, 0.0f), 768.0f);
        float y2 = fminf(fmaxf(cy + hh, 0.0f), 768.0f);

        float4 bx = m ? make_float4(x1, y1, x2 - x1, y2 - y1)
                      : make_float4(0.f, 0.f, 0.f, 0.f);
        __stcs(reinterpret_cast<float4*>(out) + idx, bx);          // streaming store

        __stcs(out + NPIX * 4 + idx, m ? 1.0f : 0.0f);
        __stcs(out + NPIX * 5 + idx, m ? sc : 0.0f);

        float2 ct = m ? make_float2(cx, cy) : make_float2(0.f, 0.f);
        __stcs(reinterpret_cast<float2*>(out + NPIX * 6) + idx, ct);
    }
}

extern "C" void kernel_launch(void* const* d_in, const int* in_sizes, int n_in,
                              void* d_out, int out_size) {
    const float* heat = (const float*)d_in[0];
    const float* box  = (const float*)d_in[1];
    // Robust input identification: heat has 23,592,960 elements, box 1,179,648.
    if (n_in >= 2 && in_sizes[0] < in_sizes[1]) {
        const float* t = heat; heat = box; box = t;
    }
    float* out = (float*)d_out;

    fused_kernel<<<dim3(NSTRIP, BB), 256>>>(heat, box, out);
}